// round 11
// baseline (speedup 1.0000x reference)
#include <cuda_runtime.h>
#include <cstdint>
#include <cstddef>

#define BATCH 64
#define DIM 512
#define MAT (DIM * DIM)
#define NUM_ITER 5
#define BK 32
#define NSTAGE (DIM / BK)   // 16
#define PSTR 20             // smem plane row stride in u32 (16 data + 4 pad)

typedef unsigned short u16;

// ---------------- device scratch: matrices as separate bf16 hi/lo planes ----------------
__device__ u16 g_Yh[2][(size_t)BATCH * MAT];
__device__ u16 g_Yl[2][(size_t)BATCH * MAT];
__device__ u16 g_Zh[2][(size_t)BATCH * MAT];
__device__ u16 g_Zl[2][(size_t)BATCH * MAT];
__device__ u16 g_Th[(size_t)BATCH * MAT];
__device__ u16 g_Tl[(size_t)BATCH * MAT];
__device__ float g_norm[BATCH];

// upper-triangular tile pairs for 4x4 grid of 128-wide tiles
__constant__ int c_ti[10] = {0, 0, 0, 0, 1, 1, 1, 2, 2, 3};
__constant__ int c_tj[10] = {0, 1, 2, 3, 1, 2, 3, 2, 3, 3};

// smem u32 offsets: one stage = 4 planes (Ah, Al, Bh, Bl), double buffered
#define P_AH 0
#define P_AL (128 * PSTR)
#define P_BH (2 * 128 * PSTR)
#define P_BL (3 * 128 * PSTR)
#define STAGE_U32 (4 * 128 * PSTR)            // 10240
#define SMEM_BYTES (2 * STAGE_U32 * 4)        // 81920

// ---------------- helpers ----------------
__device__ __forceinline__ uint32_t smem_u32(const void* p) {
    uint32_t a;
    asm("{ .reg .u64 t; cvta.to.shared.u64 t, %1; cvt.u32.u64 %0, t; }" : "=r"(a) : "l"(p));
    return a;
}
__device__ __forceinline__ void cp16(uint32_t dst, const void* src) {
    asm volatile("cp.async.cg.shared.global [%0], [%1], 16;" :: "r"(dst), "l"(src));
}
// pack: e_even -> bits[15:0], e_odd -> bits[31:16]
__device__ __forceinline__ uint32_t bfpack(float e_even, float e_odd) {
    uint32_t r;
    asm("cvt.rn.bf16x2.f32 %0, %1, %2;" : "=r"(r) : "f"(e_odd), "f"(e_even));
    return r;
}
__device__ __forceinline__ float bflo(uint32_t p) { return __uint_as_float(p << 16); }
__device__ __forceinline__ float bfhi(uint32_t p) { return __uint_as_float(p & 0xFFFF0000u); }
__device__ __forceinline__ void mma_bf16(float* c, uint32_t a0, uint32_t a1, uint32_t a2,
                                         uint32_t a3, uint32_t b0, uint32_t b1) {
    asm volatile(
        "mma.sync.aligned.m16n8k16.row.col.f32.bf16.bf16.f32 "
        "{%0,%1,%2,%3}, {%4,%5,%6,%7}, {%8,%9}, {%0,%1,%2,%3};"
        : "+f"(c[0]), "+f"(c[1]), "+f"(c[2]), "+f"(c[3])
        : "r"(a0), "r"(a1), "r"(a2), "r"(a3), "r"(b0), "r"(b1));
}
// split fp32 pair -> (hi-pair, lo-pair) packed bf16x2
__device__ __forceinline__ void splitpk(float v0, float v1, uint32_t& hp, uint32_t& lp) {
    hp = bfpack(v0, v1);
    lp = bfpack(v0 - bflo(hp), v1 - bfhi(hp));
}

// ---------------- Frobenius norm per batch ----------------
__global__ void norm_kernel(const float* __restrict__ x) {
    const int b = blockIdx.x;
    const float4* xb = (const float4*)(x + (size_t)b * MAT);
    float s = 0.f;
    for (int i = threadIdx.x; i < MAT / 4; i += blockDim.x) {
        float4 v = xb[i];
        s += v.x * v.x + v.y * v.y + v.z * v.z + v.w * v.w;
    }
    __shared__ float red[8];
    #pragma unroll
    for (int o = 16; o; o >>= 1) s += __shfl_xor_sync(0xFFFFFFFFu, s, o);
    if ((threadIdx.x & 31) == 0) red[threadIdx.x >> 5] = s;
    __syncthreads();
    if (threadIdx.x < 32) {
        s = (threadIdx.x < (int)(blockDim.x >> 5)) ? red[threadIdx.x] : 0.f;
        #pragma unroll
        for (int o = 16; o; o >>= 1) s += __shfl_xor_sync(0xFFFFFFFFu, s, o);
        if (threadIdx.x == 0) g_norm[b] = sqrtf(s);
    }
}

// ---------------- Y0 = split(x / normA) ----------------
__global__ void init_kernel(const float* __restrict__ x,
                            u16* __restrict__ Yh, u16* __restrict__ Yl) {
    const int i = blockIdx.x * blockDim.x + threadIdx.x;   // float4 id
    if (i >= BATCH * MAT / 4) return;
    const int b = i / (MAT / 4);
    const float inv = 1.0f / g_norm[b];
    float4 v = ((const float4*)x)[i];
    uint2 hp, lp;
    splitpk(v.x * inv, v.y * inv, hp.x, lp.x);
    splitpk(v.z * inv, v.w * inv, hp.y, lp.y);
    ((uint2*)Yh)[i] = hp;
    ((uint2*)Yl)[i] = lp;
}

// ---------------- Z1 = T0 = split(1.5 I - 0.5 * Y0) ----------------
__global__ void zt_kernel(const u16* __restrict__ Yh, const u16* __restrict__ Yl,
                          u16* __restrict__ Zh, u16* __restrict__ Zl) {
    const int i = blockIdx.x * blockDim.x + threadIdx.x;   // 4 elements
    if (i >= BATCH * MAT / 4) return;
    uint2 hp = ((const uint2*)Yh)[i];
    uint2 lp = ((const uint2*)Yl)[i];
    const int e0 = (4 * i) % MAT;
    const int row = e0 / DIM, col = e0 % DIM;
    float v0 = -0.5f * (bflo(hp.x) + bflo(lp.x));
    float v1 = -0.5f * (bfhi(hp.x) + bfhi(lp.x));
    float v2 = -0.5f * (bflo(hp.y) + bflo(lp.y));
    float v3 = -0.5f * (bfhi(hp.y) + bfhi(lp.y));
    if (row == col)     v0 += 1.5f;
    if (row == col + 1) v1 += 1.5f;
    if (row == col + 2) v2 += 1.5f;
    if (row == col + 3) v3 += 1.5f;
    uint2 oh, ol;
    splitpk(v0, v1, oh.x, ol.x);
    splitpk(v2, v3, oh.y, ol.y);
    ((uint2*)Zh)[i] = oh;
    ((uint2*)Zl)[i] = ol;
}

// ---------------- out = (hi + lo) * sqrt(normA) ----------------
__global__ void final_kernel(const u16* __restrict__ Yh, const u16* __restrict__ Yl,
                             float* __restrict__ out) {
    const int i = blockIdx.x * blockDim.x + threadIdx.x;   // 4 elements
    if (i >= BATCH * MAT / 4) return;
    const int b = i / (MAT / 4);
    const float s = sqrtf(g_norm[b]);
    uint2 hp = ((const uint2*)Yh)[i];
    uint2 lp = ((const uint2*)Yl)[i];
    float4 o;
    o.x = (bflo(hp.x) + bflo(lp.x)) * s;
    o.y = (bfhi(hp.x) + bfhi(lp.x)) * s;
    o.z = (bflo(hp.y) + bflo(lp.y)) * s;
    o.w = (bfhi(hp.y) + bfhi(lp.y)) * s;
    ((float4*)out)[i] = o;
}

// ---------------- all-bf16 3-term symmetric batched GEMM, pre-split operands ----------------
// C = A@B via hh + hl + lh (bf16 m16n8k16, fp32 accum). Operands arrive as bf16
// hi/lo planes; no in-kernel split. All matrices symmetric: B read as B[n][k],
// tiles ti<=tj only, mirror-stored. CTA 128x128, 256 thr, warp tile 64x32,
// BK=32, 2-stage double buffer, ONE sync per stage. Epilogue re-splits to planes.
template <int MODE>
__device__ __forceinline__ void gemm_body(
    const u16* __restrict__ Ah, const u16* __restrict__ Al,
    const u16* __restrict__ Bh, const u16* __restrict__ Bl,
    u16* __restrict__ Ch, u16* __restrict__ Cl,
    int ti, int tj, uint32_t* sm)
{
    const int bm = ti * 128;
    const int bn = tj * 128;
    const int tid = threadIdx.x;
    const int wid = tid >> 5;
    const int lane = tid & 31;
    const int gid = lane >> 2;   // 0..7
    const int tig = lane & 3;    // 0..3
    const int wm = wid >> 2;     // 0..1
    const int wn = wid & 3;      // 0..3

    const uint32_t s_base = smem_u32(sm);

    // fill: 4 planes x 512 16B-chunks; 8 chunks per thread (j=0,1 x 4 planes)
    auto fill = [&](int buf, int kc) {
        const uint32_t base = s_base + (uint32_t)buf * (STAGE_U32 * 4);
        const int koff = kc * BK;
        #pragma unroll
        for (int j = 0; j < 2; ++j) {
            const int c = tid + 256 * j;          // 0..511
            const int row = c >> 2;
            const int q = (c & 3);                // 16B chunk within row
            const uint32_t dst = base + (uint32_t)(row * PSTR + q * 4) * 4;
            const size_t asrc = (size_t)(bm + row) * DIM + koff + q * 8;
            const size_t bsrc = (size_t)(bn + row) * DIM + koff + q * 8;
            cp16(dst,                      Ah + asrc);
            cp16(dst + P_AL * 4,           Al + asrc);
            cp16(dst + P_BH * 4,           Bh + bsrc);
            cp16(dst + P_BL * 4,           Bl + bsrc);
        }
        asm volatile("cp.async.commit_group;" ::: "memory");
    };

    float acc[4][4][4];
    #pragma unroll
    for (int mf = 0; mf < 4; ++mf)
        #pragma unroll
        for (int nf = 0; nf < 4; ++nf)
            #pragma unroll
            for (int e = 0; e < 4; ++e) acc[mf][nf][e] = 0.f;

    fill(0, 0);
    asm volatile("cp.async.wait_group 0;" ::: "memory");
    __syncthreads();

    for (int s = 0; s < NSTAGE; ++s) {
        if (s + 1 < NSTAGE) fill((s + 1) & 1, s + 1);  // overlaps MMA below

        const uint32_t* pAh = sm + (s & 1) * STAGE_U32 + P_AH;
        const uint32_t* pAl = sm + (s & 1) * STAGE_U32 + P_AL;
        const uint32_t* pBh = sm + (s & 1) * STAGE_U32 + P_BH;
        const uint32_t* pBl = sm + (s & 1) * STAGE_U32 + P_BL;

        #pragma unroll
        for (int slab = 0; slab < 2; ++slab) {
            const int pb = slab * 8 + tig;
            uint32_t Bhf[4][2], Blf[4][2];
            #pragma unroll
            for (int nf = 0; nf < 4; ++nf) {
                const int r = (wn * 32 + nf * 8 + gid) * PSTR;
                Bhf[nf][0] = pBh[r + pb]; Bhf[nf][1] = pBh[r + pb + 4];
                Blf[nf][0] = pBl[r + pb]; Blf[nf][1] = pBl[r + pb + 4];
            }
            #pragma unroll
            for (int mf = 0; mf < 4; ++mf) {
                const int r0 = (wm * 64 + mf * 16 + gid) * PSTR;
                const int r1 = r0 + 8 * PSTR;
                uint32_t h0 = pAh[r0 + pb], h1 = pAh[r1 + pb];
                uint32_t h2 = pAh[r0 + pb + 4], h3 = pAh[r1 + pb + 4];
                uint32_t l0 = pAl[r0 + pb], l1 = pAl[r1 + pb];
                uint32_t l2 = pAl[r0 + pb + 4], l3 = pAl[r1 + pb + 4];
                #pragma unroll
                for (int nf = 0; nf < 4; ++nf)   // hi*hi
                    mma_bf16(acc[mf][nf], h0, h1, h2, h3, Bhf[nf][0], Bhf[nf][1]);
                #pragma unroll
                for (int nf = 0; nf < 4; ++nf)   // hi*lo
                    mma_bf16(acc[mf][nf], h0, h1, h2, h3, Blf[nf][0], Blf[nf][1]);
                #pragma unroll
                for (int nf = 0; nf < 4; ++nf)   // lo*hi
                    mma_bf16(acc[mf][nf], l0, l1, l2, l3, Bhf[nf][0], Bhf[nf][1]);
            }
        }

        if (s + 1 < NSTAGE) {
            asm volatile("cp.async.wait_group 0;" ::: "memory");
            __syncthreads();   // next buffer ready; all warps done with this one
        }
    }

    // ---------------- epilogue: mode, split to bf16 planes, main + mirror ----------------
    #pragma unroll
    for (int mf = 0; mf < 4; ++mf) {
        #pragma unroll
        for (int nf = 0; nf < 4; ++nf) {
            float* cr = acc[mf][nf];
            const int r0 = bm + wm * 64 + mf * 16 + gid;
            const int r1 = r0 + 8;
            const int cb = bn + wn * 32 + nf * 8 + 2 * tig;
            if (MODE == 1) {
                cr[0] = fmaf(cr[0], -0.5f, (cb == r0)     ? 1.5f : 0.0f);
                cr[1] = fmaf(cr[1], -0.5f, (cb + 1 == r0) ? 1.5f : 0.0f);
                cr[2] = fmaf(cr[2], -0.5f, (cb == r1)     ? 1.5f : 0.0f);
                cr[3] = fmaf(cr[3], -0.5f, (cb + 1 == r1) ? 1.5f : 0.0f);
            }
            uint32_t hp0, lp0, hp1, lp1;
            splitpk(cr[0], cr[1], hp0, lp0);
            splitpk(cr[2], cr[3], hp1, lp1);
            *(uint32_t*)(Ch + (size_t)r0 * DIM + cb) = hp0;
            *(uint32_t*)(Cl + (size_t)r0 * DIM + cb) = lp0;
            *(uint32_t*)(Ch + (size_t)r1 * DIM + cb) = hp1;
            *(uint32_t*)(Cl + (size_t)r1 * DIM + cb) = lp1;
            if (ti != tj) {  // mirror transposed (scalar u16 stores)
                Ch[(size_t)cb * DIM + r0]       = (u16)(hp0 & 0xFFFF);
                Ch[(size_t)(cb + 1) * DIM + r0] = (u16)(hp0 >> 16);
                Ch[(size_t)cb * DIM + r1]       = (u16)(hp1 & 0xFFFF);
                Ch[(size_t)(cb + 1) * DIM + r1] = (u16)(hp1 >> 16);
                Cl[(size_t)cb * DIM + r0]       = (u16)(lp0 & 0xFFFF);
                Cl[(size_t)(cb + 1) * DIM + r0] = (u16)(lp0 >> 16);
                Cl[(size_t)cb * DIM + r1]       = (u16)(lp1 & 0xFFFF);
                Cl[(size_t)(cb + 1) * DIM + r1] = (u16)(lp1 >> 16);
            }
        }
    }
}

template <int MODE>
__global__ void __launch_bounds__(256, 2) gemm_tc(
    const u16* __restrict__ Ah, const u16* __restrict__ Al,
    const u16* __restrict__ Bh, const u16* __restrict__ Bl,
    u16* __restrict__ Ch, u16* __restrict__ Cl) {
    extern __shared__ uint32_t smu[];
    const size_t off = (size_t)blockIdx.z * MAT;
    gemm_body<MODE>(Ah + off, Al + off, Bh + off, Bl + off, Ch + off, Cl + off,
                    c_ti[blockIdx.x], c_tj[blockIdx.x], smu);
}

// merged launch: y==0 -> C0 = A0@B0 ; y==1 -> C1 = A1@B1 (both MODE 0)
__global__ void __launch_bounds__(256, 2) gemm_dual(
    const u16* __restrict__ A0h, const u16* __restrict__ A0l,
    const u16* __restrict__ B0h, const u16* __restrict__ B0l,
    u16* __restrict__ C0h, u16* __restrict__ C0l,
    const u16* __restrict__ A1h, const u16* __restrict__ A1l,
    const u16* __restrict__ B1h, const u16* __restrict__ B1l,
    u16* __restrict__ C1h, u16* __restrict__ C1l) {
    extern __shared__ uint32_t smu[];
    const size_t off = (size_t)blockIdx.z * MAT;
    if (blockIdx.y == 0)
        gemm_body<0>(A0h + off, A0l + off, B0h + off, B0l + off, C0h + off, C0l + off,
                     c_ti[blockIdx.x], c_tj[blockIdx.x], smu);
    else
        gemm_body<0>(A1h + off, A1l + off, B1h + off, B1l + off, C1h + off, C1l + off,
                     c_ti[blockIdx.x], c_tj[blockIdx.x], smu);
}

// ---------------- host launcher ----------------
extern "C" void kernel_launch(void* const* d_in, const int* in_sizes, int n_in,
                              void* d_out, int out_size) {
    const float* x = (const float*)d_in[0];
    float* out = (float*)d_out;

    u16 *Yhb, *Ylb, *Zhb, *Zlb, *Thb, *Tlb;
    cudaGetSymbolAddress((void**)&Yhb, g_Yh);
    cudaGetSymbolAddress((void**)&Ylb, g_Yl);
    cudaGetSymbolAddress((void**)&Zhb, g_Zh);
    cudaGetSymbolAddress((void**)&Zlb, g_Zl);
    cudaGetSymbolAddress((void**)&Thb, g_Th);
    cudaGetSymbolAddress((void**)&Tlb, g_Tl);
    const size_t half = (size_t)BATCH * MAT;
    u16* Yh[2] = {Yhb, Yhb + half};
    u16* Yl[2] = {Ylb, Ylb + half};
    u16* Zh[2] = {Zhb, Zhb + half};
    u16* Zl[2] = {Zlb, Zlb + half};

    cudaFuncSetAttribute(gemm_tc<0>, cudaFuncAttributeMaxDynamicSharedMemorySize, SMEM_BYTES);
    cudaFuncSetAttribute(gemm_tc<1>, cudaFuncAttributeMaxDynamicSharedMemorySize, SMEM_BYTES);
    cudaFuncSetAttribute(gemm_dual, cudaFuncAttributeMaxDynamicSharedMemorySize, SMEM_BYTES);

    norm_kernel<<<BATCH, 256>>>(x);
    const int total4 = BATCH * MAT / 4;
    init_kernel<<<(total4 + 255) / 256, 256>>>(x, Yh[0], Yl[0]);

    // iter 0 (Z0 = I): T0 = 1.5I - 0.5*Y0 stored as Z[0]; Y1 = Y0 @ T0
    zt_kernel<<<(total4 + 255) / 256, 256>>>(Yh[0], Yl[0], Zh[0], Zl[0]);

    dim3 ggrid(10, 1, BATCH);
    dim3 dgrid(10, 2, BATCH);
    gemm_tc<0><<<ggrid, 256, SMEM_BYTES>>>(Yh[0], Yl[0], Zh[0], Zl[0], Yh[1], Yl[1]);
    int ycur = 1, zcur = 0;

    for (int it = 1; it < NUM_ITER; ++it) {
        // T = 1.5 I - 0.5 * Z @ Y
        gemm_tc<1><<<ggrid, 256, SMEM_BYTES>>>(Zh[zcur], Zl[zcur], Yh[ycur], Yl[ycur],
                                               Thb, Tlb);
        if (it < NUM_ITER - 1) {
            // merged: Y' = Y @ T and Z' = T @ Z
            gemm_dual<<<dgrid, 256, SMEM_BYTES>>>(
                Yh[ycur], Yl[ycur], Thb, Tlb, Yh[1 - ycur], Yl[1 - ycur],
                Thb, Tlb, Zh[zcur], Zl[zcur], Zh[1 - zcur], Zl[1 - zcur]);
            ycur ^= 1; zcur ^= 1;
        } else {
            gemm_tc<0><<<ggrid, 256, SMEM_BYTES>>>(Yh[ycur], Yl[ycur], Thb, Tlb,
                                                   Yh[1 - ycur], Yl[1 - ycur]);
            ycur ^= 1;
        }
    }

    final_kernel<<<(total4 + 255) / 256, 256>>>(Yh[ycur], Yl[ycur], out);
}

// round 12
// speedup vs baseline: 1.0527x; 1.0527x over previous
#include <cuda_runtime.h>
#include <cstdint>
#include <cstddef>

#define BATCH 64
#define DIM 512
#define MAT (DIM * DIM)
#define NUM_ITER 5
#define BK 32
#define NSTAGE (DIM / BK)   // 16
#define PSTR 20             // smem plane row stride in u32 (16 data + 4 pad)
#define TSTR 132            // transpose buffer row stride in u32

typedef unsigned short u16;

// ---------------- device scratch: matrices as separate bf16 hi/lo planes ----------------
__device__ u16 g_Yh[2][(size_t)BATCH * MAT];
__device__ u16 g_Yl[2][(size_t)BATCH * MAT];
__device__ u16 g_Zh[2][(size_t)BATCH * MAT];
__device__ u16 g_Zl[2][(size_t)BATCH * MAT];
__device__ u16 g_Th[(size_t)BATCH * MAT];
__device__ u16 g_Tl[(size_t)BATCH * MAT];
__device__ float g_norm[BATCH];

// upper-triangular tile pairs for 4x4 grid of 128-wide tiles
__constant__ int c_ti[10] = {0, 0, 0, 0, 1, 1, 1, 2, 2, 3};
__constant__ int c_tj[10] = {0, 1, 2, 3, 1, 2, 3, 2, 3, 3};

// smem u32 offsets: one stage = 4 planes (Ah, Al, Bh, Bl), double buffered.
// Epilogue reuses the whole region as a 128x132 u32 transpose tile (67.6 KB).
#define P_AH 0
#define P_AL (128 * PSTR)
#define P_BH (2 * 128 * PSTR)
#define P_BL (3 * 128 * PSTR)
#define STAGE_U32 (4 * 128 * PSTR)            // 10240
#define SMEM_BYTES (2 * STAGE_U32 * 4)        // 81920 (>= 128*TSTR*4 = 67584)

// ---------------- helpers ----------------
__device__ __forceinline__ uint32_t smem_u32(const void* p) {
    uint32_t a;
    asm("{ .reg .u64 t; cvta.to.shared.u64 t, %1; cvt.u32.u64 %0, t; }" : "=r"(a) : "l"(p));
    return a;
}
__device__ __forceinline__ void cp16(uint32_t dst, const void* src) {
    asm volatile("cp.async.cg.shared.global [%0], [%1], 16;" :: "r"(dst), "l"(src));
}
// pack: e_even -> bits[15:0], e_odd -> bits[31:16]
__device__ __forceinline__ uint32_t bfpack(float e_even, float e_odd) {
    uint32_t r;
    asm("cvt.rn.bf16x2.f32 %0, %1, %2;" : "=r"(r) : "f"(e_odd), "f"(e_even));
    return r;
}
__device__ __forceinline__ float bflo(uint32_t p) { return __uint_as_float(p << 16); }
__device__ __forceinline__ float bfhi(uint32_t p) { return __uint_as_float(p & 0xFFFF0000u); }
__device__ __forceinline__ void mma_bf16(float* c, uint32_t a0, uint32_t a1, uint32_t a2,
                                         uint32_t a3, uint32_t b0, uint32_t b1) {
    asm volatile(
        "mma.sync.aligned.m16n8k16.row.col.f32.bf16.bf16.f32 "
        "{%0,%1,%2,%3}, {%4,%5,%6,%7}, {%8,%9}, {%0,%1,%2,%3};"
        : "+f"(c[0]), "+f"(c[1]), "+f"(c[2]), "+f"(c[3])
        : "r"(a0), "r"(a1), "r"(a2), "r"(a3), "r"(b0), "r"(b1));
}
// split fp32 pair -> (hi-pair, lo-pair) packed bf16x2
__device__ __forceinline__ void splitpk(float v0, float v1, uint32_t& hp, uint32_t& lp) {
    hp = bfpack(v0, v1);
    lp = bfpack(v0 - bflo(hp), v1 - bfhi(hp));
}

// ---------------- Frobenius norm per batch ----------------
__global__ void norm_kernel(const float* __restrict__ x) {
    const int b = blockIdx.x;
    const float4* xb = (const float4*)(x + (size_t)b * MAT);
    float s = 0.f;
    for (int i = threadIdx.x; i < MAT / 4; i += blockDim.x) {
        float4 v = xb[i];
        s += v.x * v.x + v.y * v.y + v.z * v.z + v.w * v.w;
    }
    __shared__ float red[8];
    #pragma unroll
    for (int o = 16; o; o >>= 1) s += __shfl_xor_sync(0xFFFFFFFFu, s, o);
    if ((threadIdx.x & 31) == 0) red[threadIdx.x >> 5] = s;
    __syncthreads();
    if (threadIdx.x < 32) {
        s = (threadIdx.x < (int)(blockDim.x >> 5)) ? red[threadIdx.x] : 0.f;
        #pragma unroll
        for (int o = 16; o; o >>= 1) s += __shfl_xor_sync(0xFFFFFFFFu, s, o);
        if (threadIdx.x == 0) g_norm[b] = sqrtf(s);
    }
}

// ---------------- Y0 = split(x / normA) ----------------
__global__ void init_kernel(const float* __restrict__ x,
                            u16* __restrict__ Yh, u16* __restrict__ Yl) {
    const int i = blockIdx.x * blockDim.x + threadIdx.x;   // float4 id
    if (i >= BATCH * MAT / 4) return;
    const int b = i / (MAT / 4);
    const float inv = 1.0f / g_norm[b];
    float4 v = ((const float4*)x)[i];
    uint2 hp, lp;
    splitpk(v.x * inv, v.y * inv, hp.x, lp.x);
    splitpk(v.z * inv, v.w * inv, hp.y, lp.y);
    ((uint2*)Yh)[i] = hp;
    ((uint2*)Yl)[i] = lp;
}

// ---------------- Z1 = T0 = split(1.5 I - 0.5 * Y0) ----------------
__global__ void zt_kernel(const u16* __restrict__ Yh, const u16* __restrict__ Yl,
                          u16* __restrict__ Zh, u16* __restrict__ Zl) {
    const int i = blockIdx.x * blockDim.x + threadIdx.x;   // 4 elements
    if (i >= BATCH * MAT / 4) return;
    uint2 hp = ((const uint2*)Yh)[i];
    uint2 lp = ((const uint2*)Yl)[i];
    const int e0 = (4 * i) % MAT;
    const int row = e0 / DIM, col = e0 % DIM;
    float v0 = -0.5f * (bflo(hp.x) + bflo(lp.x));
    float v1 = -0.5f * (bfhi(hp.x) + bfhi(lp.x));
    float v2 = -0.5f * (bflo(hp.y) + bflo(lp.y));
    float v3 = -0.5f * (bfhi(hp.y) + bfhi(lp.y));
    if (row == col)     v0 += 1.5f;
    if (row == col + 1) v1 += 1.5f;
    if (row == col + 2) v2 += 1.5f;
    if (row == col + 3) v3 += 1.5f;
    uint2 oh, ol;
    splitpk(v0, v1, oh.x, ol.x);
    splitpk(v2, v3, oh.y, ol.y);
    ((uint2*)Zh)[i] = oh;
    ((uint2*)Zl)[i] = ol;
}

// ---------------- out = (hi + lo) * sqrt(normA) ----------------
__global__ void final_kernel(const u16* __restrict__ Yh, const u16* __restrict__ Yl,
                             float* __restrict__ out) {
    const int i = blockIdx.x * blockDim.x + threadIdx.x;   // 4 elements
    if (i >= BATCH * MAT / 4) return;
    const int b = i / (MAT / 4);
    const float s = sqrtf(g_norm[b]);
    uint2 hp = ((const uint2*)Yh)[i];
    uint2 lp = ((const uint2*)Yl)[i];
    float4 o;
    o.x = (bflo(hp.x) + bflo(lp.x)) * s;
    o.y = (bfhi(hp.x) + bfhi(lp.x)) * s;
    o.z = (bflo(hp.y) + bflo(lp.y)) * s;
    o.w = (bfhi(hp.y) + bfhi(lp.y)) * s;
    ((float4*)out)[i] = o;
}

// ---------------- all-bf16 3-term symmetric batched GEMM, pre-split operands ----------------
// C = A@B via hh + hl + lh (bf16 m16n8k16, fp32 accum). Operands arrive as bf16
// hi/lo planes; no in-kernel split. All matrices symmetric: B read as B[n][k],
// tiles ti<=tj only, mirror via SMEM TRANSPOSE + coalesced stores.
// CTA 128x128, 256 thr, warp tile 64x32, BK=32, 2-stage double buffer.
template <int MODE>
__device__ __forceinline__ void gemm_body(
    const u16* __restrict__ Ah, const u16* __restrict__ Al,
    const u16* __restrict__ Bh, const u16* __restrict__ Bl,
    u16* __restrict__ Ch, u16* __restrict__ Cl,
    int ti, int tj, uint32_t* sm)
{
    const int bm = ti * 128;
    const int bn = tj * 128;
    const int tid = threadIdx.x;
    const int wid = tid >> 5;
    const int lane = tid & 31;
    const int gid = lane >> 2;   // 0..7
    const int tig = lane & 3;    // 0..3
    const int wm = wid >> 2;     // 0..1
    const int wn = wid & 3;      // 0..3

    const uint32_t s_base = smem_u32(sm);

    auto fill = [&](int buf, int kc) {
        const uint32_t base = s_base + (uint32_t)buf * (STAGE_U32 * 4);
        const int koff = kc * BK;
        #pragma unroll
        for (int j = 0; j < 2; ++j) {
            const int c = tid + 256 * j;          // 0..511
            const int row = c >> 2;
            const int q = (c & 3);                // 16B chunk within row
            const uint32_t dst = base + (uint32_t)(row * PSTR + q * 4) * 4;
            const size_t asrc = (size_t)(bm + row) * DIM + koff + q * 8;
            const size_t bsrc = (size_t)(bn + row) * DIM + koff + q * 8;
            cp16(dst,            Ah + asrc);
            cp16(dst + P_AL * 4, Al + asrc);
            cp16(dst + P_BH * 4, Bh + bsrc);
            cp16(dst + P_BL * 4, Bl + bsrc);
        }
        asm volatile("cp.async.commit_group;" ::: "memory");
    };

    float acc[4][4][4];
    #pragma unroll
    for (int mf = 0; mf < 4; ++mf)
        #pragma unroll
        for (int nf = 0; nf < 4; ++nf)
            #pragma unroll
            for (int e = 0; e < 4; ++e) acc[mf][nf][e] = 0.f;

    fill(0, 0);
    asm volatile("cp.async.wait_group 0;" ::: "memory");
    __syncthreads();

    for (int s = 0; s < NSTAGE; ++s) {
        if (s + 1 < NSTAGE) fill((s + 1) & 1, s + 1);  // overlaps MMA below

        const uint32_t* pAh = sm + (s & 1) * STAGE_U32 + P_AH;
        const uint32_t* pAl = sm + (s & 1) * STAGE_U32 + P_AL;
        const uint32_t* pBh = sm + (s & 1) * STAGE_U32 + P_BH;
        const uint32_t* pBl = sm + (s & 1) * STAGE_U32 + P_BL;

        #pragma unroll
        for (int slab = 0; slab < 2; ++slab) {
            const int pb = slab * 8 + tig;
            uint32_t Bhf[4][2], Blf[4][2];
            #pragma unroll
            for (int nf = 0; nf < 4; ++nf) {
                const int r = (wn * 32 + nf * 8 + gid) * PSTR;
                Bhf[nf][0] = pBh[r + pb]; Bhf[nf][1] = pBh[r + pb + 4];
                Blf[nf][0] = pBl[r + pb]; Blf[nf][1] = pBl[r + pb + 4];
            }
            #pragma unroll
            for (int mf = 0; mf < 4; ++mf) {
                const int r0 = (wm * 64 + mf * 16 + gid) * PSTR;
                const int r1 = r0 + 8 * PSTR;
                uint32_t h0 = pAh[r0 + pb], h1 = pAh[r1 + pb];
                uint32_t h2 = pAh[r0 + pb + 4], h3 = pAh[r1 + pb + 4];
                uint32_t l0 = pAl[r0 + pb], l1 = pAl[r1 + pb];
                uint32_t l2 = pAl[r0 + pb + 4], l3 = pAl[r1 + pb + 4];
                #pragma unroll
                for (int nf = 0; nf < 4; ++nf)   // hi*hi
                    mma_bf16(acc[mf][nf], h0, h1, h2, h3, Bhf[nf][0], Bhf[nf][1]);
                #pragma unroll
                for (int nf = 0; nf < 4; ++nf)   // hi*lo
                    mma_bf16(acc[mf][nf], h0, h1, h2, h3, Blf[nf][0], Blf[nf][1]);
                #pragma unroll
                for (int nf = 0; nf < 4; ++nf)   // lo*hi
                    mma_bf16(acc[mf][nf], l0, l1, l2, l3, Bhf[nf][0], Bhf[nf][1]);
            }
        }

        if (s + 1 < NSTAGE) {
            asm volatile("cp.async.wait_group 0;" ::: "memory");
            __syncthreads();   // next buffer ready; all warps done with this one
        }
    }

    // ---------------- epilogue ----------------
    const bool mirror = (ti != tj);
    if (mirror) __syncthreads();   // smem reads done; safe to reuse as transpose buf

    #pragma unroll
    for (int mf = 0; mf < 4; ++mf) {
        #pragma unroll
        for (int nf = 0; nf < 4; ++nf) {
            float* cr = acc[mf][nf];
            const int lr0 = wm * 64 + mf * 16 + gid;      // local row
            const int lr1 = lr0 + 8;
            const int lc = wn * 32 + nf * 8 + 2 * tig;    // local col
            const int r0 = bm + lr0, r1 = bm + lr1, cb = bn + lc;
            if (MODE == 1) {
                cr[0] = fmaf(cr[0], -0.5f, (cb == r0)     ? 1.5f : 0.0f);
                cr[1] = fmaf(cr[1], -0.5f, (cb + 1 == r0) ? 1.5f : 0.0f);
                cr[2] = fmaf(cr[2], -0.5f, (cb == r1)     ? 1.5f : 0.0f);
                cr[3] = fmaf(cr[3], -0.5f, (cb + 1 == r1) ? 1.5f : 0.0f);
            }
            uint32_t hp0, lp0, hp1, lp1;
            splitpk(cr[0], cr[1], hp0, lp0);
            splitpk(cr[2], cr[3], hp1, lp1);
            *(uint32_t*)(Ch + (size_t)r0 * DIM + cb) = hp0;
            *(uint32_t*)(Cl + (size_t)r0 * DIM + cb) = lp0;
            *(uint32_t*)(Ch + (size_t)r1 * DIM + cb) = hp1;
            *(uint32_t*)(Cl + (size_t)r1 * DIM + cb) = lp1;
            if (mirror) {
                // sm[c][r] = hi | lo<<16 of element (r, c); banks (8*tig+gid)%32 distinct
                sm[(lc)     * TSTR + lr0] = (hp0 & 0xFFFFu) | (lp0 << 16);
                sm[(lc + 1) * TSTR + lr0] = (hp0 >> 16)     | (lp0 & 0xFFFF0000u);
                sm[(lc)     * TSTR + lr1] = (hp1 & 0xFFFFu) | (lp1 << 16);
                sm[(lc + 1) * TSTR + lr1] = (hp1 >> 16)     | (lp1 & 0xFFFF0000u);
            }
        }
    }

    if (mirror) {
        __syncthreads();
        // coalesced writeback: dest row = bn + c (0..127), dest cols = bm + 2q, 2q+1
        const int q = tid & 63;                  // u32 pair index within dest row
        #pragma unroll
        for (int j = 0; j < 32; ++j) {
            const int c = (tid >> 6) + 4 * j;
            uint2 e = *(const uint2*)(sm + c * TSTR + 2 * q);
            const size_t base = (size_t)(bn + c) * DIM + bm + 2 * q;
            *(uint32_t*)(Ch + base) = (e.x & 0xFFFFu) | ((e.y & 0xFFFFu) << 16);
            *(uint32_t*)(Cl + base) = (e.x >> 16)     | (e.y & 0xFFFF0000u);
        }
    }
}

template <int MODE>
__global__ void __launch_bounds__(256, 2) gemm_tc(
    const u16* __restrict__ Ah, const u16* __restrict__ Al,
    const u16* __restrict__ Bh, const u16* __restrict__ Bl,
    u16* __restrict__ Ch, u16* __restrict__ Cl) {
    extern __shared__ uint32_t smu[];
    const size_t off = (size_t)blockIdx.z * MAT;
    gemm_body<MODE>(Ah + off, Al + off, Bh + off, Bl + off, Ch + off, Cl + off,
                    c_ti[blockIdx.x], c_tj[blockIdx.x], smu);
}

// merged launch: y==0 -> C0 = A0@B0 ; y==1 -> C1 = A1@B1 (both MODE 0)
__global__ void __launch_bounds__(256, 2) gemm_dual(
    const u16* __restrict__ A0h, const u16* __restrict__ A0l,
    const u16* __restrict__ B0h, const u16* __restrict__ B0l,
    u16* __restrict__ C0h, u16* __restrict__ C0l,
    const u16* __restrict__ A1h, const u16* __restrict__ A1l,
    const u16* __restrict__ B1h, const u16* __restrict__ B1l,
    u16* __restrict__ C1h, u16* __restrict__ C1l) {
    extern __shared__ uint32_t smu[];
    const size_t off = (size_t)blockIdx.z * MAT;
    if (blockIdx.y == 0)
        gemm_body<0>(A0h + off, A0l + off, B0h + off, B0l + off, C0h + off, C0l + off,
                     c_ti[blockIdx.x], c_tj[blockIdx.x], smu);
    else
        gemm_body<0>(A1h + off, A1l + off, B1h + off, B1l + off, C1h + off, C1l + off,
                     c_ti[blockIdx.x], c_tj[blockIdx.x], smu);
}

// ---------------- host launcher ----------------
extern "C" void kernel_launch(void* const* d_in, const int* in_sizes, int n_in,
                              void* d_out, int out_size) {
    const float* x = (const float*)d_in[0];
    float* out = (float*)d_out;

    u16 *Yhb, *Ylb, *Zhb, *Zlb, *Thb, *Tlb;
    cudaGetSymbolAddress((void**)&Yhb, g_Yh);
    cudaGetSymbolAddress((void**)&Ylb, g_Yl);
    cudaGetSymbolAddress((void**)&Zhb, g_Zh);
    cudaGetSymbolAddress((void**)&Zlb, g_Zl);
    cudaGetSymbolAddress((void**)&Thb, g_Th);
    cudaGetSymbolAddress((void**)&Tlb, g_Tl);
    const size_t half = (size_t)BATCH * MAT;
    u16* Yh[2] = {Yhb, Yhb + half};
    u16* Yl[2] = {Ylb, Ylb + half};
    u16* Zh[2] = {Zhb, Zhb + half};
    u16* Zl[2] = {Zlb, Zlb + half};

    cudaFuncSetAttribute(gemm_tc<0>, cudaFuncAttributeMaxDynamicSharedMemorySize, SMEM_BYTES);
    cudaFuncSetAttribute(gemm_tc<1>, cudaFuncAttributeMaxDynamicSharedMemorySize, SMEM_BYTES);
    cudaFuncSetAttribute(gemm_dual, cudaFuncAttributeMaxDynamicSharedMemorySize, SMEM_BYTES);

    norm_kernel<<<BATCH, 256>>>(x);
    const int total4 = BATCH * MAT / 4;
    init_kernel<<<(total4 + 255) / 256, 256>>>(x, Yh[0], Yl[0]);

    // iter 0 (Z0 = I): T0 = 1.5I - 0.5*Y0 stored as Z[0]; Y1 = Y0 @ T0
    zt_kernel<<<(total4 + 255) / 256, 256>>>(Yh[0], Yl[0], Zh[0], Zl[0]);

    dim3 ggrid(10, 1, BATCH);
    dim3 dgrid(10, 2, BATCH);
    gemm_tc<0><<<ggrid, 256, SMEM_BYTES>>>(Yh[0], Yl[0], Zh[0], Zl[0], Yh[1], Yl[1]);
    int ycur = 1, zcur = 0;

    for (int it = 1; it < NUM_ITER; ++it) {
        // T = 1.5 I - 0.5 * Z @ Y
        gemm_tc<1><<<ggrid, 256, SMEM_BYTES>>>(Zh[zcur], Zl[zcur], Yh[ycur], Yl[ycur],
                                               Thb, Tlb);
        if (it < NUM_ITER - 1) {
            // merged: Y' = Y @ T and Z' = T @ Z
            gemm_dual<<<dgrid, 256, SMEM_BYTES>>>(
                Yh[ycur], Yl[ycur], Thb, Tlb, Yh[1 - ycur], Yl[1 - ycur],
                Thb, Tlb, Zh[zcur], Zl[zcur], Zh[1 - zcur], Zl[1 - zcur]);
            ycur ^= 1; zcur ^= 1;
        } else {
            gemm_tc<0><<<ggrid, 256, SMEM_BYTES>>>(Yh[ycur], Yl[ycur], Thb, Tlb,
                                                   Yh[1 - ycur], Yl[1 - ycur]);
            ycur ^= 1;
        }
    }

    final_kernel<<<(total4 + 255) / 256, 256>>>(Yh[ycur], Yl[ycur], out);
}

// round 13
// speedup vs baseline: 1.1282x; 1.0717x over previous
#include <cuda_runtime.h>
#include <cstdint>
#include <cstddef>

#define BATCH 64
#define DIM 512
#define MAT (DIM * DIM)
#define NUM_ITER 5
#define BK 32
#define NSTAGE (DIM / BK)   // 16
#define PSTR 20             // smem plane row stride in u32 (16 data + 4 pad)
#define TSTR 132            // transpose buffer row stride in u32

typedef unsigned short u16;

// ---------------- device scratch: matrices as separate bf16 hi/lo planes ----------------
__device__ u16 g_Yh[2][(size_t)BATCH * MAT];
__device__ u16 g_Yl[2][(size_t)BATCH * MAT];
__device__ u16 g_Zh[2][(size_t)BATCH * MAT];
__device__ u16 g_Zl[2][(size_t)BATCH * MAT];
__device__ u16 g_Th[(size_t)BATCH * MAT];
__device__ u16 g_Tl[(size_t)BATCH * MAT];
__device__ float g_norm[BATCH];

// upper-triangular tile pairs for 4x4 grid of 128-wide tiles
__constant__ int c_ti[10] = {0, 0, 0, 0, 1, 1, 1, 2, 2, 3};
__constant__ int c_tj[10] = {0, 1, 2, 3, 1, 2, 3, 2, 3, 3};

// smem u32 offsets: one stage = 4 planes (Ah, Al, Bh, Bl), double buffered.
// Epilogue reuses the whole region as a 128x132 u32 transpose tile (67.6 KB).
#define P_AH 0
#define P_AL (128 * PSTR)
#define P_BH (2 * 128 * PSTR)
#define P_BL (3 * 128 * PSTR)
#define STAGE_U32 (4 * 128 * PSTR)            // 10240
#define SMEM_BYTES (2 * STAGE_U32 * 4)        // 81920 (>= 128*TSTR*4 = 67584)

// ---------------- helpers ----------------
__device__ __forceinline__ uint32_t smem_u32(const void* p) {
    uint32_t a;
    asm("{ .reg .u64 t; cvta.to.shared.u64 t, %1; cvt.u32.u64 %0, t; }" : "=r"(a) : "l"(p));
    return a;
}
__device__ __forceinline__ void cp16(uint32_t dst, const void* src) {
    asm volatile("cp.async.cg.shared.global [%0], [%1], 16;" :: "r"(dst), "l"(src));
}
// pack: e_even -> bits[15:0], e_odd -> bits[31:16]
__device__ __forceinline__ uint32_t bfpack(float e_even, float e_odd) {
    uint32_t r;
    asm("cvt.rn.bf16x2.f32 %0, %1, %2;" : "=r"(r) : "f"(e_odd), "f"(e_even));
    return r;
}
__device__ __forceinline__ float bflo(uint32_t p) { return __uint_as_float(p << 16); }
__device__ __forceinline__ float bfhi(uint32_t p) { return __uint_as_float(p & 0xFFFF0000u); }
__device__ __forceinline__ void mma_bf16(float* c, uint32_t a0, uint32_t a1, uint32_t a2,
                                         uint32_t a3, uint32_t b0, uint32_t b1) {
    asm volatile(
        "mma.sync.aligned.m16n8k16.row.col.f32.bf16.bf16.f32 "
        "{%0,%1,%2,%3}, {%4,%5,%6,%7}, {%8,%9}, {%0,%1,%2,%3};"
        : "+f"(c[0]), "+f"(c[1]), "+f"(c[2]), "+f"(c[3])
        : "r"(a0), "r"(a1), "r"(a2), "r"(a3), "r"(b0), "r"(b1));
}
__device__ __forceinline__ void ldsm4(uint32_t& r0, uint32_t& r1, uint32_t& r2,
                                      uint32_t& r3, uint32_t addr) {
    asm volatile("ldmatrix.sync.aligned.m8n8.x4.shared.b16 {%0,%1,%2,%3}, [%4];"
                 : "=r"(r0), "=r"(r1), "=r"(r2), "=r"(r3) : "r"(addr));
}
// split fp32 pair -> (hi-pair, lo-pair) packed bf16x2
__device__ __forceinline__ void splitpk(float v0, float v1, uint32_t& hp, uint32_t& lp) {
    hp = bfpack(v0, v1);
    lp = bfpack(v0 - bflo(hp), v1 - bfhi(hp));
}

// ---------------- Frobenius norm per batch ----------------
__global__ void norm_kernel(const float* __restrict__ x) {
    const int b = blockIdx.x;
    const float4* xb = (const float4*)(x + (size_t)b * MAT);
    float s = 0.f;
    for (int i = threadIdx.x; i < MAT / 4; i += blockDim.x) {
        float4 v = xb[i];
        s += v.x * v.x + v.y * v.y + v.z * v.z + v.w * v.w;
    }
    __shared__ float red[8];
    #pragma unroll
    for (int o = 16; o; o >>= 1) s += __shfl_xor_sync(0xFFFFFFFFu, s, o);
    if ((threadIdx.x & 31) == 0) red[threadIdx.x >> 5] = s;
    __syncthreads();
    if (threadIdx.x < 32) {
        s = (threadIdx.x < (int)(blockDim.x >> 5)) ? red[threadIdx.x] : 0.f;
        #pragma unroll
        for (int o = 16; o; o >>= 1) s += __shfl_xor_sync(0xFFFFFFFFu, s, o);
        if (threadIdx.x == 0) g_norm[b] = sqrtf(s);
    }
}

// ---------------- Y0 = split(x / normA) ----------------
__global__ void init_kernel(const float* __restrict__ x,
                            u16* __restrict__ Yh, u16* __restrict__ Yl) {
    const int i = blockIdx.x * blockDim.x + threadIdx.x;   // float4 id
    if (i >= BATCH * MAT / 4) return;
    const int b = i / (MAT / 4);
    const float inv = 1.0f / g_norm[b];
    float4 v = ((const float4*)x)[i];
    uint2 hp, lp;
    splitpk(v.x * inv, v.y * inv, hp.x, lp.x);
    splitpk(v.z * inv, v.w * inv, hp.y, lp.y);
    ((uint2*)Yh)[i] = hp;
    ((uint2*)Yl)[i] = lp;
}

// ---------------- Z1 = T0 = split(1.5 I - 0.5 * Y0) ----------------
__global__ void zt_kernel(const u16* __restrict__ Yh, const u16* __restrict__ Yl,
                          u16* __restrict__ Zh, u16* __restrict__ Zl) {
    const int i = blockIdx.x * blockDim.x + threadIdx.x;   // 4 elements
    if (i >= BATCH * MAT / 4) return;
    uint2 hp = ((const uint2*)Yh)[i];
    uint2 lp = ((const uint2*)Yl)[i];
    const int e0 = (4 * i) % MAT;
    const int row = e0 / DIM, col = e0 % DIM;
    float v0 = -0.5f * (bflo(hp.x) + bflo(lp.x));
    float v1 = -0.5f * (bfhi(hp.x) + bfhi(lp.x));
    float v2 = -0.5f * (bflo(hp.y) + bflo(lp.y));
    float v3 = -0.5f * (bfhi(hp.y) + bfhi(lp.y));
    if (row == col)     v0 += 1.5f;
    if (row == col + 1) v1 += 1.5f;
    if (row == col + 2) v2 += 1.5f;
    if (row == col + 3) v3 += 1.5f;
    uint2 oh, ol;
    splitpk(v0, v1, oh.x, ol.x);
    splitpk(v2, v3, oh.y, ol.y);
    ((uint2*)Zh)[i] = oh;
    ((uint2*)Zl)[i] = ol;
}

// ---------------- out = (hi + lo) * sqrt(normA) ----------------
__global__ void final_kernel(const u16* __restrict__ Yh, const u16* __restrict__ Yl,
                             float* __restrict__ out) {
    const int i = blockIdx.x * blockDim.x + threadIdx.x;   // 4 elements
    if (i >= BATCH * MAT / 4) return;
    const int b = i / (MAT / 4);
    const float s = sqrtf(g_norm[b]);
    uint2 hp = ((const uint2*)Yh)[i];
    uint2 lp = ((const uint2*)Yl)[i];
    float4 o;
    o.x = (bflo(hp.x) + bflo(lp.x)) * s;
    o.y = (bfhi(hp.x) + bfhi(lp.x)) * s;
    o.z = (bflo(hp.y) + bflo(lp.y)) * s;
    o.w = (bfhi(hp.y) + bfhi(lp.y)) * s;
    ((float4*)out)[i] = o;
}

// ---------------- all-bf16 3-term symmetric batched GEMM, pre-split operands ----------------
// C = A@B via hh + hl + lh (bf16 m16n8k16, fp32 accum). Operands arrive as bf16
// hi/lo planes; fragments via ldmatrix.x4; MMAs grouped per mf-PAIR so each
// accumulator's reuse distance is 8 MMAs (RAW latency hidden).
// All matrices symmetric: B read as B[n][k], tiles ti<=tj only, mirror via
// SMEM transpose + coalesced stores. CTA 128x128, 256 thr, warp tile 64x32,
// BK=32, 2-stage double buffer.
template <int MODE>
__device__ __forceinline__ void gemm_body(
    const u16* __restrict__ Ah, const u16* __restrict__ Al,
    const u16* __restrict__ Bh, const u16* __restrict__ Bl,
    u16* __restrict__ Ch, u16* __restrict__ Cl,
    int ti, int tj, uint32_t* sm)
{
    const int bm = ti * 128;
    const int bn = tj * 128;
    const int tid = threadIdx.x;
    const int wid = tid >> 5;
    const int lane = tid & 31;
    const int gid = lane >> 2;   // 0..7
    const int tig = lane & 3;    // 0..3
    const int wm = wid >> 2;     // 0..1
    const int wn = wid & 3;      // 0..3

    const uint32_t s_base = smem_u32(sm);

    auto fill = [&](int buf, int kc) {
        const uint32_t base = s_base + (uint32_t)buf * (STAGE_U32 * 4);
        const int koff = kc * BK;
        #pragma unroll
        for (int j = 0; j < 2; ++j) {
            const int c = tid + 256 * j;          // 0..511
            const int row = c >> 2;
            const int q = (c & 3);                // 16B chunk within row
            const uint32_t dst = base + (uint32_t)(row * PSTR + q * 4) * 4;
            const size_t asrc = (size_t)(bm + row) * DIM + koff + q * 8;
            const size_t bsrc = (size_t)(bn + row) * DIM + koff + q * 8;
            cp16(dst,            Ah + asrc);
            cp16(dst + P_AL * 4, Al + asrc);
            cp16(dst + P_BH * 4, Bh + bsrc);
            cp16(dst + P_BL * 4, Bl + bsrc);
        }
        asm volatile("cp.async.commit_group;" ::: "memory");
    };

    float acc[4][4][4];
    #pragma unroll
    for (int mf = 0; mf < 4; ++mf)
        #pragma unroll
        for (int nf = 0; nf < 4; ++nf)
            #pragma unroll
            for (int e = 0; e < 4; ++e) acc[mf][nf][e] = 0.f;

    // ldmatrix lane offsets (bytes):
    // A x4: matrices (m0-7,k0),(m8-15,k0),(m0-7,k8),(m8-15,k8)
    const uint32_t aoff = (uint32_t)((((lane & 7) + ((lane >> 3) & 1) * 8) * PSTR
                                      + (lane >> 4) * 4) * 4);
    // B x4: matrices (nf0,k0),(nf0,k8),(nf0+1,k0),(nf0+1,k8)
    const uint32_t boff = (uint32_t)((((lane & 7) + (lane >> 4) * 8) * PSTR
                                      + ((lane >> 3) & 1) * 4) * 4);
    const uint32_t aRow = (uint32_t)(wm * 64) * PSTR * 4;   // warp A row base (bytes)
    const uint32_t bRow = (uint32_t)(wn * 32) * PSTR * 4;   // warp B row base (bytes)

    fill(0, 0);
    asm volatile("cp.async.wait_group 0;" ::: "memory");
    __syncthreads();

    for (int s = 0; s < NSTAGE; ++s) {
        if (s + 1 < NSTAGE) fill((s + 1) & 1, s + 1);  // overlaps MMA below

        const uint32_t sb = s_base + (uint32_t)(s & 1) * (STAGE_U32 * 4);
        const uint32_t bAh = sb + P_AH * 4 + aRow + aoff;
        const uint32_t bAl = sb + P_AL * 4 + aRow + aoff;
        const uint32_t bBh = sb + P_BH * 4 + bRow + boff;
        const uint32_t bBl = sb + P_BL * 4 + bRow + boff;

        #pragma unroll
        for (int slab = 0; slab < 2; ++slab) {
            const uint32_t kadd = slab * 32;          // 8 u32 = 32 bytes
            // B fragments: 2 nf per ldmatrix.x4
            uint32_t Bhf[4][2], Blf[4][2];
            #pragma unroll
            for (int nfp = 0; nfp < 2; ++nfp) {
                const uint32_t badd = (uint32_t)(nfp * 16) * PSTR * 4 + kadd;
                ldsm4(Bhf[2 * nfp][0], Bhf[2 * nfp][1],
                      Bhf[2 * nfp + 1][0], Bhf[2 * nfp + 1][1], bBh + badd);
                ldsm4(Blf[2 * nfp][0], Blf[2 * nfp][1],
                      Blf[2 * nfp + 1][0], Blf[2 * nfp + 1][1], bBl + badd);
            }
            // mf-pairs: acc reuse distance = 8 MMAs
            #pragma unroll
            for (int p = 0; p < 2; ++p) {
                const uint32_t a0add = (uint32_t)(p * 32) * PSTR * 4 + kadd;
                const uint32_t a1add = a0add + (uint32_t)16 * PSTR * 4;
                uint32_t Ah0[4], Ah1[4], Al0[4], Al1[4];
                ldsm4(Ah0[0], Ah0[1], Ah0[2], Ah0[3], bAh + a0add);
                ldsm4(Ah1[0], Ah1[1], Ah1[2], Ah1[3], bAh + a1add);
                ldsm4(Al0[0], Al0[1], Al0[2], Al0[3], bAl + a0add);
                ldsm4(Al1[0], Al1[1], Al1[2], Al1[3], bAl + a1add);
                const int m0 = 2 * p, m1 = 2 * p + 1;
                #pragma unroll
                for (int nf = 0; nf < 4; ++nf)   // hh, mf even
                    mma_bf16(acc[m0][nf], Ah0[0], Ah0[1], Ah0[2], Ah0[3],
                             Bhf[nf][0], Bhf[nf][1]);
                #pragma unroll
                for (int nf = 0; nf < 4; ++nf)   // hh, mf odd
                    mma_bf16(acc[m1][nf], Ah1[0], Ah1[1], Ah1[2], Ah1[3],
                             Bhf[nf][0], Bhf[nf][1]);
                #pragma unroll
                for (int nf = 0; nf < 4; ++nf)   // hl, mf even
                    mma_bf16(acc[m0][nf], Ah0[0], Ah0[1], Ah0[2], Ah0[3],
                             Blf[nf][0], Blf[nf][1]);
                #pragma unroll
                for (int nf = 0; nf < 4; ++nf)   // hl, mf odd
                    mma_bf16(acc[m1][nf], Ah1[0], Ah1[1], Ah1[2], Ah1[3],
                             Blf[nf][0], Blf[nf][1]);
                #pragma unroll
                for (int nf = 0; nf < 4; ++nf)   // lh, mf even
                    mma_bf16(acc[m0][nf], Al0[0], Al0[1], Al0[2], Al0[3],
                             Bhf[nf][0], Bhf[nf][1]);
                #pragma unroll
                for (int nf = 0; nf < 4; ++nf)   // lh, mf odd
                    mma_bf16(acc[m1][nf], Al1[0], Al1[1], Al1[2], Al1[3],
                             Bhf[nf][0], Bhf[nf][1]);
            }
        }

        if (s + 1 < NSTAGE) {
            asm volatile("cp.async.wait_group 0;" ::: "memory");
            __syncthreads();   // next buffer ready; all warps done with this one
        }
    }

    // ---------------- epilogue ----------------
    const bool mirror = (ti != tj);
    if (mirror) __syncthreads();   // smem reads done; safe to reuse as transpose buf

    #pragma unroll
    for (int mf = 0; mf < 4; ++mf) {
        #pragma unroll
        for (int nf = 0; nf < 4; ++nf) {
            float* cr = acc[mf][nf];
            const int lr0 = wm * 64 + mf * 16 + gid;      // local row
            const int lr1 = lr0 + 8;
            const int lc = wn * 32 + nf * 8 + 2 * tig;    // local col
            const int r0 = bm + lr0, r1 = bm + lr1, cb = bn + lc;
            if (MODE == 1) {
                cr[0] = fmaf(cr[0], -0.5f, (cb == r0)     ? 1.5f : 0.0f);
                cr[1] = fmaf(cr[1], -0.5f, (cb + 1 == r0) ? 1.5f : 0.0f);
                cr[2] = fmaf(cr[2], -0.5f, (cb == r1)     ? 1.5f : 0.0f);
                cr[3] = fmaf(cr[3], -0.5f, (cb + 1 == r1) ? 1.5f : 0.0f);
            }
            uint32_t hp0, lp0, hp1, lp1;
            splitpk(cr[0], cr[1], hp0, lp0);
            splitpk(cr[2], cr[3], hp1, lp1);
            *(uint32_t*)(Ch + (size_t)r0 * DIM + cb) = hp0;
            *(uint32_t*)(Cl + (size_t)r0 * DIM + cb) = lp0;
            *(uint32_t*)(Ch + (size_t)r1 * DIM + cb) = hp1;
            *(uint32_t*)(Cl + (size_t)r1 * DIM + cb) = lp1;
            if (mirror) {
                // sm[c][r] = hi | lo<<16 of element (r, c); banks (8*tig+gid)%32 distinct
                sm[(lc)     * TSTR + lr0] = (hp0 & 0xFFFFu) | (lp0 << 16);
                sm[(lc + 1) * TSTR + lr0] = (hp0 >> 16)     | (lp0 & 0xFFFF0000u);
                sm[(lc)     * TSTR + lr1] = (hp1 & 0xFFFFu) | (lp1 << 16);
                sm[(lc + 1) * TSTR + lr1] = (hp1 >> 16)     | (lp1 & 0xFFFF0000u);
            }
        }
    }

    if (mirror) {
        __syncthreads();
        // coalesced writeback: dest row = bn + c (0..127), dest cols = bm + 2q, 2q+1
        const int q = tid & 63;                  // u32 pair index within dest row
        #pragma unroll
        for (int j = 0; j < 32; ++j) {
            const int c = (tid >> 6) + 4 * j;
            uint2 e = *(const uint2*)(sm + c * TSTR + 2 * q);
            const size_t base = (size_t)(bn + c) * DIM + bm + 2 * q;
            *(uint32_t*)(Ch + base) = (e.x & 0xFFFFu) | ((e.y & 0xFFFFu) << 16);
            *(uint32_t*)(Cl + base) = (e.x >> 16)     | (e.y & 0xFFFF0000u);
        }
    }
}

template <int MODE>
__global__ void __launch_bounds__(256, 2) gemm_tc(
    const u16* __restrict__ Ah, const u16* __restrict__ Al,
    const u16* __restrict__ Bh, const u16* __restrict__ Bl,
    u16* __restrict__ Ch, u16* __restrict__ Cl) {
    extern __shared__ uint32_t smu[];
    const size_t off = (size_t)blockIdx.z * MAT;
    gemm_body<MODE>(Ah + off, Al + off, Bh + off, Bl + off, Ch + off, Cl + off,
                    c_ti[blockIdx.x], c_tj[blockIdx.x], smu);
}

// merged launch: y==0 -> C0 = A0@B0 ; y==1 -> C1 = A1@B1 (both MODE 0)
__global__ void __launch_bounds__(256, 2) gemm_dual(
    const u16* __restrict__ A0h, const u16* __restrict__ A0l,
    const u16* __restrict__ B0h, const u16* __restrict__ B0l,
    u16* __restrict__ C0h, u16* __restrict__ C0l,
    const u16* __restrict__ A1h, const u16* __restrict__ A1l,
    const u16* __restrict__ B1h, const u16* __restrict__ B1l,
    u16* __restrict__ C1h, u16* __restrict__ C1l) {
    extern __shared__ uint32_t smu[];
    const size_t off = (size_t)blockIdx.z * MAT;
    if (blockIdx.y == 0)
        gemm_body<0>(A0h + off, A0l + off, B0h + off, B0l + off, C0h + off, C0l + off,
                     c_ti[blockIdx.x], c_tj[blockIdx.x], smu);
    else
        gemm_body<0>(A1h + off, A1l + off, B1h + off, B1l + off, C1h + off, C1l + off,
                     c_ti[blockIdx.x], c_tj[blockIdx.x], smu);
}

// ---------------- host launcher ----------------
extern "C" void kernel_launch(void* const* d_in, const int* in_sizes, int n_in,
                              void* d_out, int out_size) {
    const float* x = (const float*)d_in[0];
    float* out = (float*)d_out;

    u16 *Yhb, *Ylb, *Zhb, *Zlb, *Thb, *Tlb;
    cudaGetSymbolAddress((void**)&Yhb, g_Yh);
    cudaGetSymbolAddress((void**)&Ylb, g_Yl);
    cudaGetSymbolAddress((void**)&Zhb, g_Zh);
    cudaGetSymbolAddress((void**)&Zlb, g_Zl);
    cudaGetSymbolAddress((void**)&Thb, g_Th);
    cudaGetSymbolAddress((void**)&Tlb, g_Tl);
    const size_t half = (size_t)BATCH * MAT;
    u16* Yh[2] = {Yhb, Yhb + half};
    u16* Yl[2] = {Ylb, Ylb + half};
    u16* Zh[2] = {Zhb, Zhb + half};
    u16* Zl[2] = {Zlb, Zlb + half};

    cudaFuncSetAttribute(gemm_tc<0>, cudaFuncAttributeMaxDynamicSharedMemorySize, SMEM_BYTES);
    cudaFuncSetAttribute(gemm_tc<1>, cudaFuncAttributeMaxDynamicSharedMemorySize, SMEM_BYTES);
    cudaFuncSetAttribute(gemm_dual, cudaFuncAttributeMaxDynamicSharedMemorySize, SMEM_BYTES);

    norm_kernel<<<BATCH, 256>>>(x);
    const int total4 = BATCH * MAT / 4;
    init_kernel<<<(total4 + 255) / 256, 256>>>(x, Yh[0], Yl[0]);

    // iter 0 (Z0 = I): T0 = 1.5I - 0.5*Y0 stored as Z[0]; Y1 = Y0 @ T0
    zt_kernel<<<(total4 + 255) / 256, 256>>>(Yh[0], Yl[0], Zh[0], Zl[0]);

    dim3 ggrid(10, 1, BATCH);
    dim3 dgrid(10, 2, BATCH);
    gemm_tc<0><<<ggrid, 256, SMEM_BYTES>>>(Yh[0], Yl[0], Zh[0], Zl[0], Yh[1], Yl[1]);
    int ycur = 1, zcur = 0;

    for (int it = 1; it < NUM_ITER; ++it) {
        // T = 1.5 I - 0.5 * Z @ Y
        gemm_tc<1><<<ggrid, 256, SMEM_BYTES>>>(Zh[zcur], Zl[zcur], Yh[ycur], Yl[ycur],
                                               Thb, Tlb);
        if (it < NUM_ITER - 1) {
            // merged: Y' = Y @ T and Z' = T @ Z
            gemm_dual<<<dgrid, 256, SMEM_BYTES>>>(
                Yh[ycur], Yl[ycur], Thb, Tlb, Yh[1 - ycur], Yl[1 - ycur],
                Thb, Tlb, Zh[zcur], Zl[zcur], Zh[1 - zcur], Zl[1 - zcur]);
            ycur ^= 1; zcur ^= 1;
        } else {
            gemm_tc<0><<<ggrid, 256, SMEM_BYTES>>>(Yh[ycur], Yl[ycur], Thb, Tlb,
                                                   Yh[1 - ycur], Yl[1 - ycur]);
            ycur ^= 1;
        }
    }

    final_kernel<<<(total4 + 255) / 256, 256>>>(Yh[ycur], Yl[ycur], out);
}

// round 14
// speedup vs baseline: 1.1318x; 1.0032x over previous
#include <cuda_runtime.h>
#include <cstdint>
#include <cstddef>

#define BATCH 64
#define DIM 512
#define MAT (DIM * DIM)
#define NUM_ITER 5
#define BK 32
#define NSTAGE (DIM / BK)   // 16
#define GSTR 68             // row-group stride in u32: Ah16|Al16|Bh16|Bl16|pad4
#define O_AH 0
#define O_AL 16
#define O_BH 32
#define O_BL 48
#define TSTR 132            // transpose buffer row stride in u32
#define NBUF 3

typedef unsigned short u16;

// ---------------- device scratch: matrices as separate bf16 hi/lo planes ----------------
__device__ u16 g_Yh[2][(size_t)BATCH * MAT];
__device__ u16 g_Yl[2][(size_t)BATCH * MAT];
__device__ u16 g_Zh[2][(size_t)BATCH * MAT];
__device__ u16 g_Zl[2][(size_t)BATCH * MAT];
__device__ u16 g_Th[(size_t)BATCH * MAT];
__device__ u16 g_Tl[(size_t)BATCH * MAT];
__device__ float g_norm[BATCH];

// upper-triangular tile pairs for 4x4 grid of 128-wide tiles
__constant__ int c_ti[10] = {0, 0, 0, 0, 1, 1, 1, 2, 2, 3};
__constant__ int c_tj[10] = {0, 1, 2, 3, 1, 2, 3, 2, 3, 3};

#define STAGE_U32 (128 * GSTR)                 // 8704
#define SMEM_BYTES (NBUF * STAGE_U32 * 4)      // 104448 (2 CTAs/SM; >= 128*TSTR*4)

// ---------------- helpers ----------------
__device__ __forceinline__ uint32_t smem_u32(const void* p) {
    uint32_t a;
    asm("{ .reg .u64 t; cvta.to.shared.u64 t, %1; cvt.u32.u64 %0, t; }" : "=r"(a) : "l"(p));
    return a;
}
__device__ __forceinline__ void cp16(uint32_t dst, const void* src) {
    asm volatile("cp.async.cg.shared.global [%0], [%1], 16;" :: "r"(dst), "l"(src));
}
// pack: e_even -> bits[15:0], e_odd -> bits[31:16]
__device__ __forceinline__ uint32_t bfpack(float e_even, float e_odd) {
    uint32_t r;
    asm("cvt.rn.bf16x2.f32 %0, %1, %2;" : "=r"(r) : "f"(e_odd), "f"(e_even));
    return r;
}
__device__ __forceinline__ float bflo(uint32_t p) { return __uint_as_float(p << 16); }
__device__ __forceinline__ float bfhi(uint32_t p) { return __uint_as_float(p & 0xFFFF0000u); }
__device__ __forceinline__ void mma_bf16(float* c, uint32_t a0, uint32_t a1, uint32_t a2,
                                         uint32_t a3, uint32_t b0, uint32_t b1) {
    asm volatile(
        "mma.sync.aligned.m16n8k16.row.col.f32.bf16.bf16.f32 "
        "{%0,%1,%2,%3}, {%4,%5,%6,%7}, {%8,%9}, {%0,%1,%2,%3};"
        : "+f"(c[0]), "+f"(c[1]), "+f"(c[2]), "+f"(c[3])
        : "r"(a0), "r"(a1), "r"(a2), "r"(a3), "r"(b0), "r"(b1));
}
__device__ __forceinline__ void ldsm4(uint32_t& r0, uint32_t& r1, uint32_t& r2,
                                      uint32_t& r3, uint32_t addr) {
    asm volatile("ldmatrix.sync.aligned.m8n8.x4.shared.b16 {%0,%1,%2,%3}, [%4];"
                 : "=r"(r0), "=r"(r1), "=r"(r2), "=r"(r3) : "r"(addr));
}
// split fp32 pair -> (hi-pair, lo-pair) packed bf16x2
__device__ __forceinline__ void splitpk(float v0, float v1, uint32_t& hp, uint32_t& lp) {
    hp = bfpack(v0, v1);
    lp = bfpack(v0 - bflo(hp), v1 - bfhi(hp));
}

// ---------------- Frobenius norm per batch ----------------
__global__ void norm_kernel(const float* __restrict__ x) {
    const int b = blockIdx.x;
    const float4* xb = (const float4*)(x + (size_t)b * MAT);
    float s = 0.f;
    for (int i = threadIdx.x; i < MAT / 4; i += blockDim.x) {
        float4 v = xb[i];
        s += v.x * v.x + v.y * v.y + v.z * v.z + v.w * v.w;
    }
    __shared__ float red[8];
    #pragma unroll
    for (int o = 16; o; o >>= 1) s += __shfl_xor_sync(0xFFFFFFFFu, s, o);
    if ((threadIdx.x & 31) == 0) red[threadIdx.x >> 5] = s;
    __syncthreads();
    if (threadIdx.x < 32) {
        s = (threadIdx.x < (int)(blockDim.x >> 5)) ? red[threadIdx.x] : 0.f;
        #pragma unroll
        for (int o = 16; o; o >>= 1) s += __shfl_xor_sync(0xFFFFFFFFu, s, o);
        if (threadIdx.x == 0) g_norm[b] = sqrtf(s);
    }
}

// ---------------- Y0 = split(x / normA) ----------------
__global__ void init_kernel(const float* __restrict__ x,
                            u16* __restrict__ Yh, u16* __restrict__ Yl) {
    const int i = blockIdx.x * blockDim.x + threadIdx.x;   // float4 id
    if (i >= BATCH * MAT / 4) return;
    const int b = i / (MAT / 4);
    const float inv = 1.0f / g_norm[b];
    float4 v = ((const float4*)x)[i];
    uint2 hp, lp;
    splitpk(v.x * inv, v.y * inv, hp.x, lp.x);
    splitpk(v.z * inv, v.w * inv, hp.y, lp.y);
    ((uint2*)Yh)[i] = hp;
    ((uint2*)Yl)[i] = lp;
}

// ---------------- Z1 = T0 = split(1.5 I - 0.5 * Y0) ----------------
__global__ void zt_kernel(const u16* __restrict__ Yh, const u16* __restrict__ Yl,
                          u16* __restrict__ Zh, u16* __restrict__ Zl) {
    const int i = blockIdx.x * blockDim.x + threadIdx.x;   // 4 elements
    if (i >= BATCH * MAT / 4) return;
    uint2 hp = ((const uint2*)Yh)[i];
    uint2 lp = ((const uint2*)Yl)[i];
    const int e0 = (4 * i) % MAT;
    const int row = e0 / DIM, col = e0 % DIM;
    float v0 = -0.5f * (bflo(hp.x) + bflo(lp.x));
    float v1 = -0.5f * (bfhi(hp.x) + bfhi(lp.x));
    float v2 = -0.5f * (bflo(hp.y) + bflo(lp.y));
    float v3 = -0.5f * (bfhi(hp.y) + bfhi(lp.y));
    if (row == col)     v0 += 1.5f;
    if (row == col + 1) v1 += 1.5f;
    if (row == col + 2) v2 += 1.5f;
    if (row == col + 3) v3 += 1.5f;
    uint2 oh, ol;
    splitpk(v0, v1, oh.x, ol.x);
    splitpk(v2, v3, oh.y, ol.y);
    ((uint2*)Zh)[i] = oh;
    ((uint2*)Zl)[i] = ol;
}

// ---------------- out = (hi + lo) * sqrt(normA) ----------------
__global__ void final_kernel(const u16* __restrict__ Yh, const u16* __restrict__ Yl,
                             float* __restrict__ out) {
    const int i = blockIdx.x * blockDim.x + threadIdx.x;   // 4 elements
    if (i >= BATCH * MAT / 4) return;
    const int b = i / (MAT / 4);
    const float s = sqrtf(g_norm[b]);
    uint2 hp = ((const uint2*)Yh)[i];
    uint2 lp = ((const uint2*)Yl)[i];
    float4 o;
    o.x = (bflo(hp.x) + bflo(lp.x)) * s;
    o.y = (bfhi(hp.x) + bfhi(lp.x)) * s;
    o.z = (bflo(hp.y) + bflo(lp.y)) * s;
    o.w = (bfhi(hp.y) + bfhi(lp.y)) * s;
    ((float4*)out)[i] = o;
}

// ---------------- all-bf16 3-term symmetric batched GEMM, pre-split operands ----------------
// C = A@B via hh + hl + lh (bf16 m16n8k16, fp32 accum). Row-group smem layout
// (Ah|Al|Bh|Bl per row, stride 68 u32) -> 3-stage ring fits 2 CTAs/SM; waits
// target loads issued TWO mma-phases ago (wait_group 1). ldmatrix fragments,
// mf-pair MMA grouping (acc reuse distance 8). Symmetric: B read as B[n][k],
// tiles ti<=tj only, mirror via smem transpose + coalesced stores.
template <int MODE>
__device__ __forceinline__ void gemm_body(
    const u16* __restrict__ Ah, const u16* __restrict__ Al,
    const u16* __restrict__ Bh, const u16* __restrict__ Bl,
    u16* __restrict__ Ch, u16* __restrict__ Cl,
    int ti, int tj, uint32_t* sm)
{
    const int bm = ti * 128;
    const int bn = tj * 128;
    const int tid = threadIdx.x;
    const int wid = tid >> 5;
    const int lane = tid & 31;
    const int gid = lane >> 2;   // 0..7
    const int tig = lane & 3;    // 0..3
    const int wm = wid >> 2;     // 0..1
    const int wn = wid & 3;      // 0..3

    const uint32_t s_base = smem_u32(sm);

    auto fill = [&](int buf, int kc) {
        const uint32_t base = s_base + (uint32_t)buf * (STAGE_U32 * 4);
        const int koff = kc * BK;
        #pragma unroll
        for (int j = 0; j < 2; ++j) {
            const int c = tid + 256 * j;          // 0..511
            const int row = c >> 2;
            const int q = (c & 3);                // 16B chunk within 64B plane row
            const uint32_t dst = base + (uint32_t)(row * GSTR + q * 4) * 4;
            const size_t asrc = (size_t)(bm + row) * DIM + koff + q * 8;
            const size_t bsrc = (size_t)(bn + row) * DIM + koff + q * 8;
            cp16(dst + O_AH * 4, Ah + asrc);
            cp16(dst + O_AL * 4, Al + asrc);
            cp16(dst + O_BH * 4, Bh + bsrc);
            cp16(dst + O_BL * 4, Bl + bsrc);
        }
        asm volatile("cp.async.commit_group;" ::: "memory");
    };

    float acc[4][4][4];
    #pragma unroll
    for (int mf = 0; mf < 4; ++mf)
        #pragma unroll
        for (int nf = 0; nf < 4; ++nf)
            #pragma unroll
            for (int e = 0; e < 4; ++e) acc[mf][nf][e] = 0.f;

    // ldmatrix lane offsets (bytes) within a stage:
    // A x4: matrices (m0-7,k0),(m8-15,k0),(m0-7,k8),(m8-15,k8)
    const uint32_t aoff = (uint32_t)((((lane & 7) + ((lane >> 3) & 1) * 8) * GSTR
                                      + (lane >> 4) * 4) * 4);
    // B x4: matrices (nf0,k0),(nf0,k8),(nf0+1,k0),(nf0+1,k8)
    const uint32_t boff = (uint32_t)((((lane & 7) + (lane >> 4) * 8) * GSTR
                                      + ((lane >> 3) & 1) * 4) * 4);
    const uint32_t aRow = (uint32_t)(wm * 64) * GSTR * 4;   // warp A row base (bytes)
    const uint32_t bRow = (uint32_t)(wn * 32) * GSTR * 4;   // warp B row base (bytes)

    fill(0, 0);
    fill(1, 1);

    for (int s = 0; s < NSTAGE; ++s) {
        if (s < NSTAGE - 1) asm volatile("cp.async.wait_group 1;" ::: "memory");
        else                asm volatile("cp.async.wait_group 0;" ::: "memory");
        __syncthreads();   // buffer s ready; all warps done with MMA(s-1)

        if (s + 2 < NSTAGE) fill((s + 2) % NBUF, s + 2);  // overwrites buf of s-1: safe

        const uint32_t sb = s_base + (uint32_t)(s % NBUF) * (STAGE_U32 * 4);
        const uint32_t bAh = sb + O_AH * 4 + aRow + aoff;
        const uint32_t bAl = sb + O_AL * 4 + aRow + aoff;
        const uint32_t bBh = sb + O_BH * 4 + bRow + boff;
        const uint32_t bBl = sb + O_BL * 4 + bRow + boff;

        #pragma unroll
        for (int slab = 0; slab < 2; ++slab) {
            const uint32_t kadd = slab * 32;          // 8 u32 = 32 bytes
            // B fragments: 2 nf per ldmatrix.x4
            uint32_t Bhf[4][2], Blf[4][2];
            #pragma unroll
            for (int nfp = 0; nfp < 2; ++nfp) {
                const uint32_t badd = (uint32_t)(nfp * 16) * GSTR * 4 + kadd;
                ldsm4(Bhf[2 * nfp][0], Bhf[2 * nfp][1],
                      Bhf[2 * nfp + 1][0], Bhf[2 * nfp + 1][1], bBh + badd);
                ldsm4(Blf[2 * nfp][0], Blf[2 * nfp][1],
                      Blf[2 * nfp + 1][0], Blf[2 * nfp + 1][1], bBl + badd);
            }
            // mf-pairs: acc reuse distance = 8 MMAs
            #pragma unroll
            for (int p = 0; p < 2; ++p) {
                const uint32_t a0add = (uint32_t)(p * 32) * GSTR * 4 + kadd;
                const uint32_t a1add = a0add + (uint32_t)16 * GSTR * 4;
                uint32_t Ah0[4], Ah1[4], Al0[4], Al1[4];
                ldsm4(Ah0[0], Ah0[1], Ah0[2], Ah0[3], bAh + a0add);
                ldsm4(Ah1[0], Ah1[1], Ah1[2], Ah1[3], bAh + a1add);
                ldsm4(Al0[0], Al0[1], Al0[2], Al0[3], bAl + a0add);
                ldsm4(Al1[0], Al1[1], Al1[2], Al1[3], bAl + a1add);
                const int m0 = 2 * p, m1 = 2 * p + 1;
                #pragma unroll
                for (int nf = 0; nf < 4; ++nf)   // hh, mf even
                    mma_bf16(acc[m0][nf], Ah0[0], Ah0[1], Ah0[2], Ah0[3],
                             Bhf[nf][0], Bhf[nf][1]);
                #pragma unroll
                for (int nf = 0; nf < 4; ++nf)   // hh, mf odd
                    mma_bf16(acc[m1][nf], Ah1[0], Ah1[1], Ah1[2], Ah1[3],
                             Bhf[nf][0], Bhf[nf][1]);
                #pragma unroll
                for (int nf = 0; nf < 4; ++nf)   // hl, mf even
                    mma_bf16(acc[m0][nf], Ah0[0], Ah0[1], Ah0[2], Ah0[3],
                             Blf[nf][0], Blf[nf][1]);
                #pragma unroll
                for (int nf = 0; nf < 4; ++nf)   // hl, mf odd
                    mma_bf16(acc[m1][nf], Ah1[0], Ah1[1], Ah1[2], Ah1[3],
                             Blf[nf][0], Blf[nf][1]);
                #pragma unroll
                for (int nf = 0; nf < 4; ++nf)   // lh, mf even
                    mma_bf16(acc[m0][nf], Al0[0], Al0[1], Al0[2], Al0[3],
                             Bhf[nf][0], Bhf[nf][1]);
                #pragma unroll
                for (int nf = 0; nf < 4; ++nf)   // lh, mf odd
                    mma_bf16(acc[m1][nf], Al1[0], Al1[1], Al1[2], Al1[3],
                             Bhf[nf][0], Bhf[nf][1]);
            }
        }
    }

    // ---------------- epilogue ----------------
    const bool mirror = (ti != tj);
    if (mirror) __syncthreads();   // smem reads done; safe to reuse as transpose buf

    #pragma unroll
    for (int mf = 0; mf < 4; ++mf) {
        #pragma unroll
        for (int nf = 0; nf < 4; ++nf) {
            float* cr = acc[mf][nf];
            const int lr0 = wm * 64 + mf * 16 + gid;      // local row
            const int lr1 = lr0 + 8;
            const int lc = wn * 32 + nf * 8 + 2 * tig;    // local col
            const int r0 = bm + lr0, r1 = bm + lr1, cb = bn + lc;
            if (MODE == 1) {
                cr[0] = fmaf(cr[0], -0.5f, (cb == r0)     ? 1.5f : 0.0f);
                cr[1] = fmaf(cr[1], -0.5f, (cb + 1 == r0) ? 1.5f : 0.0f);
                cr[2] = fmaf(cr[2], -0.5f, (cb == r1)     ? 1.5f : 0.0f);
                cr[3] = fmaf(cr[3], -0.5f, (cb + 1 == r1) ? 1.5f : 0.0f);
            }
            uint32_t hp0, lp0, hp1, lp1;
            splitpk(cr[0], cr[1], hp0, lp0);
            splitpk(cr[2], cr[3], hp1, lp1);
            *(uint32_t*)(Ch + (size_t)r0 * DIM + cb) = hp0;
            *(uint32_t*)(Cl + (size_t)r0 * DIM + cb) = lp0;
            *(uint32_t*)(Ch + (size_t)r1 * DIM + cb) = hp1;
            *(uint32_t*)(Cl + (size_t)r1 * DIM + cb) = lp1;
            if (mirror) {
                // sm[c][r] = hi | lo<<16 of element (r, c); banks distinct per group
                sm[(lc)     * TSTR + lr0] = (hp0 & 0xFFFFu) | (lp0 << 16);
                sm[(lc + 1) * TSTR + lr0] = (hp0 >> 16)     | (lp0 & 0xFFFF0000u);
                sm[(lc)     * TSTR + lr1] = (hp1 & 0xFFFFu) | (lp1 << 16);
                sm[(lc + 1) * TSTR + lr1] = (hp1 >> 16)     | (lp1 & 0xFFFF0000u);
            }
        }
    }

    if (mirror) {
        __syncthreads();
        // coalesced writeback: dest row = bn + c (0..127), dest cols = bm + 2q, 2q+1
        const int q = tid & 63;                  // u32 pair index within dest row
        #pragma unroll
        for (int j = 0; j < 32; ++j) {
            const int c = (tid >> 6) + 4 * j;
            uint2 e = *(const uint2*)(sm + c * TSTR + 2 * q);
            const size_t base = (size_t)(bn + c) * DIM + bm + 2 * q;
            *(uint32_t*)(Ch + base) = (e.x & 0xFFFFu) | ((e.y & 0xFFFFu) << 16);
            *(uint32_t*)(Cl + base) = (e.x >> 16)     | (e.y & 0xFFFF0000u);
        }
    }
}

template <int MODE>
__global__ void __launch_bounds__(256, 2) gemm_tc(
    const u16* __restrict__ Ah, const u16* __restrict__ Al,
    const u16* __restrict__ Bh, const u16* __restrict__ Bl,
    u16* __restrict__ Ch, u16* __restrict__ Cl) {
    extern __shared__ uint32_t smu[];
    const size_t off = (size_t)blockIdx.z * MAT;
    gemm_body<MODE>(Ah + off, Al + off, Bh + off, Bl + off, Ch + off, Cl + off,
                    c_ti[blockIdx.x], c_tj[blockIdx.x], smu);
}

// merged launch: y==0 -> C0 = A0@B0 ; y==1 -> C1 = A1@B1 (both MODE 0)
__global__ void __launch_bounds__(256, 2) gemm_dual(
    const u16* __restrict__ A0h, const u16* __restrict__ A0l,
    const u16* __restrict__ B0h, const u16* __restrict__ B0l,
    u16* __restrict__ C0h, u16* __restrict__ C0l,
    const u16* __restrict__ A1h, const u16* __restrict__ A1l,
    const u16* __restrict__ B1h, const u16* __restrict__ B1l,
    u16* __restrict__ C1h, u16* __restrict__ C1l) {
    extern __shared__ uint32_t smu[];
    const size_t off = (size_t)blockIdx.z * MAT;
    if (blockIdx.y == 0)
        gemm_body<0>(A0h + off, A0l + off, B0h + off, B0l + off, C0h + off, C0l + off,
                     c_ti[blockIdx.x], c_tj[blockIdx.x], smu);
    else
        gemm_body<0>(A1h + off, A1l + off, B1h + off, B1l + off, C1h + off, C1l + off,
                     c_ti[blockIdx.x], c_tj[blockIdx.x], smu);
}

// ---------------- host launcher ----------------
extern "C" void kernel_launch(void* const* d_in, const int* in_sizes, int n_in,
                              void* d_out, int out_size) {
    const float* x = (const float*)d_in[0];
    float* out = (float*)d_out;

    u16 *Yhb, *Ylb, *Zhb, *Zlb, *Thb, *Tlb;
    cudaGetSymbolAddress((void**)&Yhb, g_Yh);
    cudaGetSymbolAddress((void**)&Ylb, g_Yl);
    cudaGetSymbolAddress((void**)&Zhb, g_Zh);
    cudaGetSymbolAddress((void**)&Zlb, g_Zl);
    cudaGetSymbolAddress((void**)&Thb, g_Th);
    cudaGetSymbolAddress((void**)&Tlb, g_Tl);
    const size_t half = (size_t)BATCH * MAT;
    u16* Yh[2] = {Yhb, Yhb + half};
    u16* Yl[2] = {Ylb, Ylb + half};
    u16* Zh[2] = {Zhb, Zhb + half};
    u16* Zl[2] = {Zlb, Zlb + half};

    cudaFuncSetAttribute(gemm_tc<0>, cudaFuncAttributeMaxDynamicSharedMemorySize, SMEM_BYTES);
    cudaFuncSetAttribute(gemm_tc<1>, cudaFuncAttributeMaxDynamicSharedMemorySize, SMEM_BYTES);
    cudaFuncSetAttribute(gemm_dual, cudaFuncAttributeMaxDynamicSharedMemorySize, SMEM_BYTES);

    norm_kernel<<<BATCH, 256>>>(x);
    const int total4 = BATCH * MAT / 4;
    init_kernel<<<(total4 + 255) / 256, 256>>>(x, Yh[0], Yl[0]);

    // iter 0 (Z0 = I): T0 = 1.5I - 0.5*Y0 stored as Z[0]; Y1 = Y0 @ T0
    zt_kernel<<<(total4 + 255) / 256, 256>>>(Yh[0], Yl[0], Zh[0], Zl[0]);

    dim3 ggrid(10, 1, BATCH);
    dim3 dgrid(10, 2, BATCH);
    gemm_tc<0><<<ggrid, 256, SMEM_BYTES>>>(Yh[0], Yl[0], Zh[0], Zl[0], Yh[1], Yl[1]);
    int ycur = 1, zcur = 0;

    for (int it = 1; it < NUM_ITER; ++it) {
        // T = 1.5 I - 0.5 * Z @ Y
        gemm_tc<1><<<ggrid, 256, SMEM_BYTES>>>(Zh[zcur], Zl[zcur], Yh[ycur], Yl[ycur],
                                               Thb, Tlb);
        if (it < NUM_ITER - 1) {
            // merged: Y' = Y @ T and Z' = T @ Z
            gemm_dual<<<dgrid, 256, SMEM_BYTES>>>(
                Yh[ycur], Yl[ycur], Thb, Tlb, Yh[1 - ycur], Yl[1 - ycur],
                Thb, Tlb, Zh[zcur], Zl[zcur], Zh[1 - zcur], Zl[1 - zcur]);
            ycur ^= 1; zcur ^= 1;
        } else {
            gemm_tc<0><<<ggrid, 256, SMEM_BYTES>>>(Yh[ycur], Yl[ycur], Thb, Tlb,
                                                   Yh[1 - ycur], Yl[1 - ycur]);
            ycur ^= 1;
        }
    }

    final_kernel<<<(total4 + 255) / 256, 256>>>(Yh[ycur], Yl[ycur], out);
}